// round 14
// baseline (speedup 1.0000x reference)
#include <cuda_runtime.h>
#include <cuda_fp16.h>
#include <cstdint>

// NeuralClickModel, round 12.
// P,Q = e@[W1|W2]^T precomputed for ALL 20 steps in ONE fp16 GEMM.
// Entire 20-step recurrence fused into ONE persistent kernel (96 CTAs,
// single wave) with device-wide sense-reversing spin barriers:
//   per step:  Gh = h@Whh^T (96 MMA tiles) | barrier | GRU elem + y + next A | barrier

#define SLATE_ 20
#define NSEQ  4096
#define DD    256
#define KC    64
#define NKCH  4
#define MROWS_PRE 81920
#define NPRE  1536
#define NH    768
#define NBLK_REC 96          // 32 M-tiles x 3 N-tiles, single wave

#define ABLK  (128 * KC)
#define BBLK  (256 * KC)
#define ABYT  (ABLK * 2)
#define BBYT  (BBLK * 2)
#define BUFB  (ABYT + BBYT)
#define SMTOT (2 * BUFB)     // 96 KB

// -------- device scratch (static; no allocation) --------
__device__ __align__(16) __half g_Ae[MROWS_PRE * DD];
__device__ __align__(16) __half g_Bpre[NPRE * DD];
__device__ __align__(16) __half g_Bh[NH * DD];
__device__ __align__(16) __half g_Ah[NSEQ * DD];
__device__ __align__(16) __half g_Gpre[(size_t)MROWS_PRE * NPRE];
__device__ __align__(16) float  g_Gh[NSEQ * NH];
__device__ float g_h[NSEQ * DD];
__device__ float g_m[NSEQ];
__device__ unsigned g_bar_cnt;
__device__ unsigned g_bar_gen;

// -------- helpers --------
__device__ __forceinline__ uint32_t h2_as_u32(__half2 h) {
    union { __half2 h2; uint32_t u; } cvt;
    cvt.h2 = h;
    return cvt.u;
}
__device__ __forceinline__ uint32_t smem_u32(const void* p) {
    uint32_t a;
    asm("{ .reg .u64 t; cvta.to.shared.u64 t, %1; cvt.u32.u64 %0, t; }" : "=r"(a) : "l"(p));
    return a;
}
__device__ __forceinline__ int swz(int byt) { return byt ^ ((byt >> 3) & 0x70); }
__device__ __forceinline__ void cp16(uint32_t s, const void* g) {
    asm volatile("cp.async.cg.shared.global [%0], [%1], 16;" :: "r"(s), "l"(g) : "memory");
}
__device__ __forceinline__ void cp_commit() {
    asm volatile("cp.async.commit_group;" ::: "memory");
}
template <int N> __device__ __forceinline__ void cp_wait() {
    asm volatile("cp.async.wait_group %0;" :: "n"(N) : "memory");
}
__device__ __forceinline__ void ldm4(uint32_t addr, uint32_t* r) {
    asm volatile("ldmatrix.sync.aligned.m8n8.x4.shared.b16 {%0,%1,%2,%3}, [%4];"
                 : "=r"(r[0]), "=r"(r[1]), "=r"(r[2]), "=r"(r[3]) : "r"(addr));
}
__device__ __forceinline__ void mma_fp16(float* d, const uint32_t* a, const uint32_t* b) {
    asm volatile(
        "mma.sync.aligned.m16n8k16.row.col.f32.f16.f16.f32 "
        "{%0,%1,%2,%3}, {%4,%5,%6,%7}, {%8,%9}, {%0,%1,%2,%3};"
        : "+f"(d[0]), "+f"(d[1]), "+f"(d[2]), "+f"(d[3])
        : "r"(a[0]), "r"(a[1]), "r"(a[2]), "r"(a[3]), "r"(b[0]), "r"(b[1]));
}
__device__ __forceinline__ int a_idx(int r, int k) {
    int blk = (r >> 7) * NKCH + (k >> 6);
    return blk * ABLK + (swz((r & 127) * 128 + (k & 63) * 2) >> 1);
}
__device__ __forceinline__ int b_idx(int n, int k) {
    int blk = (n >> 8) * NKCH + (k >> 6);
    return blk * BBLK + (swz((n & 255) * 128 + (k & 63) * 2) >> 1);
}
__device__ __forceinline__ float sigmoidf_(float x) { return 1.0f / (1.0f + __expf(-x)); }

// device-wide barrier: all NBLK_REC CTAs resident (single wave)
__device__ __forceinline__ void grid_bar(unsigned& mygen) {
    __syncthreads();
    if (threadIdx.x == 0) {
        __threadfence();
        unsigned a = atomicAdd(&g_bar_cnt, 1u);
        if (a == NBLK_REC - 1) {
            g_bar_cnt = 0u;
            __threadfence();
            atomicAdd(&g_bar_gen, 1u);
        } else {
            while (*(volatile unsigned*)&g_bar_gen == mygen) { }
            __threadfence();
        }
    }
    mygen++;
    __syncthreads();
}

// -------- weight prep --------
__global__ void wsplit_pre_kernel(const float* __restrict__ W_ih) {
    int idx = blockIdx.x * blockDim.x + threadIdx.x;
    if (idx == 0) { g_bar_cnt = 0u; g_bar_gen = 0u; }   // reset barrier per launch
    int n = idx >> 8, k = idx & 255;
    float w = (n < NH) ? W_ih[n * 512 + k] : W_ih[(n - NH) * 512 + 256 + k];
    g_Bpre[b_idx(n, k)] = __float2half_rn(w);
}
__global__ void wsplit_h_kernel(const float* __restrict__ W_hh) {
    int idx = blockIdx.x * blockDim.x + threadIdx.x;
    int n = idx >> 8, k = idx & 255;
    g_Bh[b_idx(n, k)] = __float2half_rn(W_hh[n * 256 + k]);
}

// -------- embedding gather for all steps --------
__global__ void prep_e_kernel(const int* __restrict__ item_idxs,
                              const float* __restrict__ item_table) {
    int r = blockIdx.x * 8 + (threadIdx.x >> 5);
    int lane = threadIdx.x & 31;
    int n = r & (NSEQ - 1);
    int s = r >> 12;
    int iidx = item_idxs[n * SLATE_ + s];
    const float* src = item_table + (size_t)iidx * DD + lane * 8;
    float4 v0 = *(const float4*)src;
    float4 v1 = *(const float4*)(src + 4);
    uint4 h4;
    h4.x = h2_as_u32(__floats2half2_rn(v0.x, v0.y));
    h4.y = h2_as_u32(__floats2half2_rn(v0.z, v0.w));
    h4.z = h2_as_u32(__floats2half2_rn(v1.x, v1.y));
    h4.w = h2_as_u32(__floats2half2_rn(v1.z, v1.w));
    *(uint4*)(g_Ae + a_idx(r, lane * 8)) = h4;
}

// -------- h0 / m0 prep (warp per sequence) --------
__global__ void prep_h_kernel(const int* __restrict__ user_idxs,
                              const float* __restrict__ user_table) {
    int n = blockIdx.x * 8 + (threadIdx.x >> 5);
    int lane = threadIdx.x & 31;
    const float* src = user_table + (size_t)user_idxs[n] * DD + lane * 8;
    float4 v0 = *(const float4*)src;
    float4 v1 = *(const float4*)(src + 4);
    *(float4*)(g_h + n * DD + lane * 8) = v0;
    *(float4*)(g_h + n * DD + lane * 8 + 4) = v1;
    uint4 h4;
    h4.x = h2_as_u32(__floats2half2_rn(v0.x, v0.y));
    h4.y = h2_as_u32(__floats2half2_rn(v0.z, v0.w));
    h4.z = h2_as_u32(__floats2half2_rn(v1.x, v1.y));
    h4.w = h2_as_u32(__floats2half2_rn(v1.z, v1.w));
    *(uint4*)(g_Ah + a_idx(n, lane * 8)) = h4;
    if (lane == 0) g_m[n] = 1.0f;
}

// -------- GEMM body: C[128 x 256-tile] = A @ B^T, K=256 --------
template <typename OT>
__device__ __forceinline__ void gemm_body(const __half* __restrict__ gA,
                                          const __half* __restrict__ gB,
                                          OT* __restrict__ gC, int cpitch,
                                          int mt, int nt) {
    extern __shared__ char smem[];
    const uint32_t sb = smem_u32(smem);
    const int tid = threadIdx.x;
    const int lane = tid & 31;
    const int warp = tid >> 5;
    const int wm = warp & 1;
    const int wn = warp >> 1;

    const char* pA = (const char*)(gA + (size_t)mt * NKCH * ABLK);
    const char* pB = (const char*)(gB + (size_t)nt * NKCH * BBLK);

    float acc[4][8][4];
#pragma unroll
    for (int mi = 0; mi < 4; mi++)
#pragma unroll
        for (int ni = 0; ni < 8; ni++)
#pragma unroll
            for (int q = 0; q < 4; q++) acc[mi][ni][q] = 0.0f;

    const int arow  = wm * 64 + (lane & 15);
    const int acolb = (lane >> 4) * 16;
    const int brow  = wn * 64 + ((lane >> 4) << 3) + (lane & 7);
    const int bcolb = ((lane >> 3) & 1) * 16;

#pragma unroll
    for (int i = 0; i < 4; i++) {
        int o = (tid + i * 256) * 16;
        cp16(sb + o, pA + o);
    }
#pragma unroll
    for (int i = 0; i < 8; i++) {
        int o = (tid + i * 256) * 16;
        cp16(sb + ABYT + o, pB + o);
    }
    cp_commit();

#pragma unroll 1
    for (int c = 0; c < NKCH; c++) {
        const int buf = c & 1;
        if (c + 1 < NKCH) {
            const uint32_t d2 = sb + (buf ^ 1) * BUFB;
#pragma unroll
            for (int i = 0; i < 4; i++) {
                int o = (tid + i * 256) * 16;
                cp16(d2 + o, pA + (c + 1) * ABYT + o);
            }
#pragma unroll
            for (int i = 0; i < 8; i++) {
                int o = (tid + i * 256) * 16;
                cp16(d2 + ABYT + o, pB + (c + 1) * BBYT + o);
            }
            cp_commit();
            cp_wait<1>();
        } else {
            cp_wait<0>();
        }
        __syncthreads();

        const uint32_t base = sb + buf * BUFB;
#pragma unroll
        for (int kk = 0; kk < 4; kk++) {
            uint32_t Af[4][4];
#pragma unroll
            for (int mi = 0; mi < 4; mi++)
                ldm4(base + swz((arow + mi * 16) * 128 + kk * 32 + acolb), Af[mi]);
            uint32_t Bf[4][4];
#pragma unroll
            for (int j = 0; j < 4; j++)
                ldm4(base + ABYT + swz((brow + j * 16) * 128 + kk * 32 + bcolb), Bf[j]);
#pragma unroll
            for (int mi = 0; mi < 4; mi++)
#pragma unroll
                for (int j = 0; j < 4; j++) {
                    mma_fp16(acc[mi][2 * j],     Af[mi], Bf[j]);
                    mma_fp16(acc[mi][2 * j + 1], Af[mi], Bf[j] + 2);
                }
        }
        __syncthreads();
    }

    const int grow = mt * 128 + wm * 64 + (lane >> 2);
    const int gcol = nt * 256 + wn * 64 + 2 * (lane & 3);
#pragma unroll
    for (int mi = 0; mi < 4; mi++) {
#pragma unroll
        for (int ni = 0; ni < 8; ni++) {
            size_t p0 = (size_t)(grow + mi * 16) * cpitch + gcol + ni * 8;
            if constexpr (sizeof(OT) == 2) {
                *(__half2*)((__half*)gC + p0) =
                    __floats2half2_rn(acc[mi][ni][0], acc[mi][ni][1]);
                *(__half2*)((__half*)gC + p0 + (size_t)8 * cpitch) =
                    __floats2half2_rn(acc[mi][ni][2], acc[mi][ni][3]);
            } else {
                *(float2*)((float*)gC + p0) =
                    make_float2(acc[mi][ni][0], acc[mi][ni][1]);
                *(float2*)((float*)gC + p0 + (size_t)8 * cpitch) =
                    make_float2(acc[mi][ni][2], acc[mi][ni][3]);
            }
        }
    }
}

__global__ void __launch_bounds__(256, 1) gemm_pre_kernel() {
    gemm_body<__half>(g_Ae, g_Bpre, g_Gpre, NPRE, blockIdx.x, blockIdx.y);
}

// -------- persistent recurrence: 20 x (GEMM | bar | elem | bar) --------
__global__ void __launch_bounds__(256, 1)
recur_kernel(const float* __restrict__ b_ih,
             const float* __restrict__ b_hh,
             const float* __restrict__ W_out,
             const float* __restrict__ b_out,
             float* __restrict__ out) {
    const int tid = threadIdx.x;
    const int lane = tid & 31;
    const int mt = blockIdx.x & 31;      // 32 M-tiles
    const int nt = blockIdx.x >> 5;      // 3 N-tiles
    const int wgid = blockIdx.x * 8 + (tid >> 5);   // 0..767
    unsigned mygen = 0;
    const float bo = __ldg(b_out);

#pragma unroll 1
    for (int s = 0; s < SLATE_; s++) {
        // phase 1: Gh = h @ Whh^T for this CTA's tile
        gemm_body<float>(g_Ah, g_Bh, g_Gh, NH, mt, nt);
        grid_bar(mygen);

        // phase 2: GRU elementwise, warp per sequence, strided over 768 warps
#pragma unroll 1
        for (int n = wgid; n < NSEQ; n += NBLK_REC * 8) {
            const __half* Pr = g_Gpre + (size_t)(s * NSEQ + n) * NPRE;
            const float* Gh = g_Gh + (size_t)n * NH;
            const float m = g_m[n];
            float yp = 0.0f;
#pragma unroll
            for (int i = 0; i < 8; i++) {
                int d = lane + i * 32;
                float P_r = __half2float(Pr[d]);
                float P_z = __half2float(Pr[256 + d]);
                float P_n = __half2float(Pr[512 + d]);
                float Q_r = __half2float(Pr[768 + d]);
                float Q_z = __half2float(Pr[1024 + d]);
                float Q_n = __half2float(Pr[1280 + d]);
                float r = sigmoidf_(P_r + m * Q_r + __ldg(b_ih + d) + Gh[d] + __ldg(b_hh + d));
                float z = sigmoidf_(P_z + m * Q_z + __ldg(b_ih + 256 + d) + Gh[256 + d] +
                                    __ldg(b_hh + 256 + d));
                float nv = tanhf(P_n + m * Q_n + __ldg(b_ih + 512 + d) +
                                 r * (Gh[512 + d] + __ldg(b_hh + 512 + d)));
                float ho = g_h[n * DD + d];
                float hv = fmaf(z, ho - nv, nv);
                g_h[n * DD + d] = hv;
                g_Ah[a_idx(n, d)] = __float2half_rn(hv);
                yp = fmaf(hv, __ldg(W_out + d), yp);
            }
#pragma unroll
            for (int off = 16; off > 0; off >>= 1)
                yp += __shfl_xor_sync(0xffffffffu, yp, off);
            if (lane == 0) {
                float y = yp + bo;
                out[n * SLATE_ + s] = y;
                g_m[n] = sigmoidf_(y);
            }
        }
        grid_bar(mygen);
    }
}

extern "C" void kernel_launch(void* const* d_in, const int* in_sizes, int n_in,
                              void* d_out, int out_size) {
    const int*   item_idxs  = (const int*)d_in[0];
    const int*   user_idxs  = (const int*)d_in[1];
    /* d_in[2] = responses (unused) */
    const float* item_table = (const float*)d_in[3];
    const float* user_table = (const float*)d_in[4];
    const float* W_ih       = (const float*)d_in[5];
    const float* W_hh       = (const float*)d_in[6];
    const float* b_ih       = (const float*)d_in[7];
    const float* b_hh       = (const float*)d_in[8];
    const float* W_out      = (const float*)d_in[9];
    const float* b_out      = (const float*)d_in[10];
    float* out = (float*)d_out;

    cudaFuncSetAttribute(gemm_pre_kernel,
                         cudaFuncAttributeMaxDynamicSharedMemorySize, SMTOT);
    cudaFuncSetAttribute(recur_kernel,
                         cudaFuncAttributeMaxDynamicSharedMemorySize, SMTOT);

    wsplit_pre_kernel<<<NPRE * 256 / 256, 256>>>(W_ih);
    wsplit_h_kernel<<<NH * 256 / 256, 256>>>(W_hh);
    prep_e_kernel<<<MROWS_PRE / 8, 256>>>(item_idxs, item_table);
    prep_h_kernel<<<NSEQ / 8, 256>>>(user_idxs, user_table);

    gemm_pre_kernel<<<dim3(MROWS_PRE / 128, NPRE / 256), 256, SMTOT>>>();

    recur_kernel<<<NBLK_REC, 256, SMTOT>>>(b_ih, b_hh, W_out, b_out, out);
}

// round 17
// speedup vs baseline: 2.0106x; 2.0106x over previous
#include <cuda_runtime.h>
#include <cuda_fp16.h>
#include <cstdint>

// NeuralClickModel, round 15.
// P,Q = e@[W1|W2]^T for all 20 steps in one persistent B-resident fp16 GEMM.
// Per step: ONE fused kernel (128 CTAs, M=32/CTA, N=768): Gh = h@Whh^T with
// register-resident accumulators whose (r,z,n) gate values for a given (seq,d)
// live in the SAME thread; GRU gates + y + state update run in-register, with
// P/Q, h, biases, m prefetched to smem via cp.async DURING the GEMM.

#define SLATE_ 20
#define NSEQ  4096
#define DD    256
#define KC    64
#define NKCH  4
#define MROWS_PRE 81920
#define NPRE  1536
#define NH    768

#define ABLK  (128 * KC)
#define BBLK  (256 * KC)
#define ABYT  (ABLK * 2)        // 16 KB
#define BBYT  (BBLK * 2)        // 32 KB

// persistent gemm_pre
#define PRE_NT 6
#define PRE_CTAS_PER_NT 24
#define PRE_MT 640
#define PRE_SMEM (4 * BBYT + 4 * ABYT)   // 128K B + 64K A ring = 192K

// fused step kernel smem map (bytes)
#define FS_A    0                          // 16384  (32 x 256 fp16, [kc][row][k] swz)
#define FS_B    16384                      // 2 x 32768 ring
#define FS_PQ   (16384 + 65536)            // 32 rows x 1544 halfs (pad) = 98816
#define FS_H    (FS_PQ + 98816)            // 32 rows x 260 floats (pad) = 33280
#define FS_CON  (FS_H + 33280)             // b_ih 768f | b_hh 768f | W_out 256f | m 32f = 7296
#define FS_Y    (FS_CON + 7296)            // ypart 32*4 floats = 512
#define FS_TOT  (FS_Y + 512)               // 221 KB total
#define PQ_PITCH 1544
#define H_PITCH  260

// -------- device scratch --------
__device__ __align__(16) __half g_Ae[MROWS_PRE * DD];
__device__ __align__(16) __half g_Bpre[NPRE * DD];
__device__ __align__(16) __half g_Bh[NH * DD];
__device__ __align__(16) __half g_Ah[NSEQ * DD];
__device__ __align__(16) __half g_Gpre[(size_t)MROWS_PRE * NPRE];
__device__ __align__(16) float  g_h[NSEQ * DD];
__device__ __align__(16) float  g_m[NSEQ];

// -------- helpers --------
__device__ __forceinline__ uint32_t h2_as_u32(__half2 h) {
    union { __half2 h2; uint32_t u; } cvt;
    cvt.h2 = h;
    return cvt.u;
}
__device__ __forceinline__ uint32_t smem_u32(const void* p) {
    uint32_t a;
    asm("{ .reg .u64 t; cvta.to.shared.u64 t, %1; cvt.u32.u64 %0, t; }" : "=r"(a) : "l"(p));
    return a;
}
__device__ __forceinline__ int swz(int byt) { return byt ^ ((byt >> 3) & 0x70); }
__device__ __forceinline__ void cp16(uint32_t s, const void* g) {
    asm volatile("cp.async.cg.shared.global [%0], [%1], 16;" :: "r"(s), "l"(g) : "memory");
}
__device__ __forceinline__ void cp_commit() {
    asm volatile("cp.async.commit_group;" ::: "memory");
}
template <int N> __device__ __forceinline__ void cp_wait() {
    asm volatile("cp.async.wait_group %0;" :: "n"(N) : "memory");
}
__device__ __forceinline__ void cp_wait_d(int n) {
    if (n == 0) cp_wait<0>();
    else if (n == 1) cp_wait<1>();
    else cp_wait<2>();
}
__device__ __forceinline__ void ldm4(uint32_t addr, uint32_t* r) {
    asm volatile("ldmatrix.sync.aligned.m8n8.x4.shared.b16 {%0,%1,%2,%3}, [%4];"
                 : "=r"(r[0]), "=r"(r[1]), "=r"(r[2]), "=r"(r[3]) : "r"(addr));
}
__device__ __forceinline__ void mma_fp16(float* d, const uint32_t* a, const uint32_t* b) {
    asm volatile(
        "mma.sync.aligned.m16n8k16.row.col.f32.f16.f16.f32 "
        "{%0,%1,%2,%3}, {%4,%5,%6,%7}, {%8,%9}, {%0,%1,%2,%3};"
        : "+f"(d[0]), "+f"(d[1]), "+f"(d[2]), "+f"(d[3])
        : "r"(a[0]), "r"(a[1]), "r"(a[2]), "r"(a[3]), "r"(b[0]), "r"(b[1]));
}
__device__ __forceinline__ int a_idx(int r, int k) {
    int blk = (r >> 7) * NKCH + (k >> 6);
    return blk * ABLK + (swz((r & 127) * 128 + (k & 63) * 2) >> 1);
}
__device__ __forceinline__ int b_idx(int n, int k) {
    int blk = (n >> 8) * NKCH + (k >> 6);
    return blk * BBLK + (swz((n & 255) * 128 + (k & 63) * 2) >> 1);
}
__device__ __forceinline__ float sigmoidf_(float x) { return 1.0f / (1.0f + __expf(-x)); }

// -------- weight prep --------
__global__ void wsplit_pre_kernel(const float* __restrict__ W_ih) {
    int idx = blockIdx.x * blockDim.x + threadIdx.x;
    int n = idx >> 8, k = idx & 255;
    float w = (n < NH) ? W_ih[n * 512 + k] : W_ih[(n - NH) * 512 + 256 + k];
    g_Bpre[b_idx(n, k)] = __float2half_rn(w);
}
__global__ void wsplit_h_kernel(const float* __restrict__ W_hh) {
    int idx = blockIdx.x * blockDim.x + threadIdx.x;
    int n = idx >> 8, k = idx & 255;
    g_Bh[b_idx(n, k)] = __float2half_rn(W_hh[n * 256 + k]);
}

// -------- embedding gather for all steps --------
__global__ void prep_e_kernel(const int* __restrict__ item_idxs,
                              const float* __restrict__ item_table) {
    int r = blockIdx.x * 8 + (threadIdx.x >> 5);
    int lane = threadIdx.x & 31;
    int n = r & (NSEQ - 1);
    int s = r >> 12;
    int iidx = item_idxs[n * SLATE_ + s];
    const float* src = item_table + (size_t)iidx * DD + lane * 8;
    float4 v0 = *(const float4*)src;
    float4 v1 = *(const float4*)(src + 4);
    uint4 h4;
    h4.x = h2_as_u32(__floats2half2_rn(v0.x, v0.y));
    h4.y = h2_as_u32(__floats2half2_rn(v0.z, v0.w));
    h4.z = h2_as_u32(__floats2half2_rn(v1.x, v1.y));
    h4.w = h2_as_u32(__floats2half2_rn(v1.z, v1.w));
    *(uint4*)(g_Ae + a_idx(r, lane * 8)) = h4;
}

// -------- h0 / m0 prep --------
__global__ void prep_h_kernel(const int* __restrict__ user_idxs,
                              const float* __restrict__ user_table) {
    int n = blockIdx.x * 8 + (threadIdx.x >> 5);
    int lane = threadIdx.x & 31;
    const float* src = user_table + (size_t)user_idxs[n] * DD + lane * 8;
    float4 v0 = *(const float4*)src;
    float4 v1 = *(const float4*)(src + 4);
    *(float4*)(g_h + n * DD + lane * 8) = v0;
    *(float4*)(g_h + n * DD + lane * 8 + 4) = v1;
    uint4 h4;
    h4.x = h2_as_u32(__floats2half2_rn(v0.x, v0.y));
    h4.y = h2_as_u32(__floats2half2_rn(v0.z, v0.w));
    h4.z = h2_as_u32(__floats2half2_rn(v1.x, v1.y));
    h4.w = h2_as_u32(__floats2half2_rn(v1.z, v1.w));
    *(uint4*)(g_Ah + a_idx(n, lane * 8)) = h4;
    if (lane == 0) g_m[n] = 1.0f;
}

// -------- gemm_pre: persistent, B-resident in smem, depth-4 A ring --------
__global__ void __launch_bounds__(256, 1) gemm_pre_kernel() {
    extern __shared__ char smem[];
    const uint32_t sB = smem_u32(smem);
    const uint32_t sA = sB + 4 * BBYT;
    const int tid = threadIdx.x;
    const int lane = tid & 31;
    const int warp = tid >> 5;
    const int wm = warp & 1;
    const int wn = warp >> 1;
    const int nt = blockIdx.x % PRE_NT;
    const int ctam = blockIdx.x / PRE_NT;

    // stage full B n-tile (128 KB) — group 0
    const char* gB = (const char*)g_Bpre + (size_t)nt * 4 * BBYT;
#pragma unroll
    for (int i = 0; i < 32; i++) { int o = (tid + i * 256) * 16; cp16(sB + o, gB + o); }
    cp_commit();
    // first 3 A chunks of first tile — groups 1..3
    {
        const char* gA0 = (const char*)g_Ae + (size_t)ctam * 4 * ABYT;
#pragma unroll
        for (int c = 0; c < 3; c++) {
#pragma unroll
            for (int i = 0; i < 4; i++) {
                int o = (tid + i * 256) * 16;
                cp16(sA + c * ABYT + o, gA0 + c * ABYT + o);
            }
            cp_commit();
        }
    }

    float acc[4][8][4];
#pragma unroll
    for (int mi = 0; mi < 4; mi++)
#pragma unroll
        for (int ni = 0; ni < 8; ni++)
#pragma unroll
            for (int q = 0; q < 4; q++) acc[mi][ni][q] = 0.0f;

    const int arow  = wm * 64 + (lane & 15);
    const int acolb = (lane >> 4) * 16;
    const int brow  = wn * 64 + ((lane >> 4) << 3) + (lane & 7);
    const int bcolb = ((lane >> 3) & 1) * 16;

    int j = 0;  // global chunk index (4 per tile)
#pragma unroll 1
    for (int t = ctam; t < PRE_MT; t += PRE_CTAS_PER_NT) {
#pragma unroll 1
        for (int kc = 0; kc < 4; kc++, j++) {
            cp_wait<2>();
            __syncthreads();
            // prefetch chunk j+3 into ring buffer (j+3)&3
            {
                int pj = j + 3;
                int ptile = ctam + (pj >> 2) * PRE_CTAS_PER_NT;
                if (ptile < PRE_MT) {
                    const char* gA = (const char*)g_Ae + (size_t)ptile * 4 * ABYT
                                     + (size_t)(pj & 3) * ABYT;
                    uint32_t dst = sA + (pj & 3) * ABYT;
#pragma unroll
                    for (int i = 0; i < 4; i++) {
                        int o = (tid + i * 256) * 16;
                        cp16(dst + o, gA + o);
                    }
                }
                cp_commit();  // empty commits keep group counting uniform
            }
            const uint32_t abase = sA + (j & 3) * ABYT;
            const uint32_t bbase = sB + kc * BBYT;
#pragma unroll
            for (int kk = 0; kk < 4; kk++) {
                uint32_t Af[4][4];
#pragma unroll
                for (int mi = 0; mi < 4; mi++)
                    ldm4(abase + swz((arow + mi * 16) * 128 + kk * 32 + acolb), Af[mi]);
                uint32_t Bf[4][4];
#pragma unroll
                for (int jj = 0; jj < 4; jj++)
                    ldm4(bbase + swz((brow + jj * 16) * 128 + kk * 32 + bcolb), Bf[jj]);
#pragma unroll
                for (int mi = 0; mi < 4; mi++)
#pragma unroll
                    for (int jj = 0; jj < 4; jj++) {
                        mma_fp16(acc[mi][2 * jj],     Af[mi], Bf[jj]);
                        mma_fp16(acc[mi][2 * jj + 1], Af[mi], Bf[jj] + 2);
                    }
            }
            __syncthreads();
        }
        // epilogue for tile t
        const int grow = t * 128 + wm * 64 + (lane >> 2);
        const int gcol = nt * 256 + wn * 64 + 2 * (lane & 3);
#pragma unroll
        for (int mi = 0; mi < 4; mi++) {
#pragma unroll
            for (int ni = 0; ni < 8; ni++) {
                size_t p0 = (size_t)(grow + mi * 16) * NPRE + gcol + ni * 8;
                *(__half2*)(g_Gpre + p0) =
                    __floats2half2_rn(acc[mi][ni][0], acc[mi][ni][1]);
                *(__half2*)(g_Gpre + p0 + (size_t)8 * NPRE) =
                    __floats2half2_rn(acc[mi][ni][2], acc[mi][ni][3]);
                acc[mi][ni][0] = 0.0f; acc[mi][ni][1] = 0.0f;
                acc[mi][ni][2] = 0.0f; acc[mi][ni][3] = 0.0f;
            }
        }
    }
}

// -------- fused per-step kernel: Gh GEMM (M=32, N=768) + GRU elem --------
__global__ void __launch_bounds__(256, 1)
fused_step_kernel(const float* __restrict__ b_ih,
                  const float* __restrict__ b_hh,
                  const float* __restrict__ W_out,
                  const float* __restrict__ b_out,
                  float* __restrict__ out, int s) {
    extern __shared__ char smem[];
    const uint32_t sb = smem_u32(smem);
    const int tid = threadIdx.x;
    const int lane = tid & 31;
    const int warp = tid >> 5;
    const int wm = warp & 1;       // 2 x m16
    const int wn = warp >> 1;      // 4 x n64 (within each 256-col gate block)
    const int n0 = blockIdx.x * 32;

    // ---- group 1: A (this CTA's 32 rows of g_Ah) + B block 0 ----
#pragma unroll
    for (int i = 0; i < 4; i++) {
        int idx = tid + i * 256;           // 0..1023
        int kc = idx >> 8, inner = idx & 255;
        const char* src = (const char*)g_Ah + ((size_t)(n0 >> 7) * 4 + kc) * ABYT
                          + (size_t)(n0 & 127) * 128 + inner * 16;
        cp16(sb + FS_A + idx * 16, src);
    }
#pragma unroll
    for (int i = 0; i < 8; i++) {
        int o = (tid + i * 256) * 16;
        cp16(sb + FS_B + o, (const char*)g_Bh + o);
    }
    cp_commit();

    // ---- group 2: PQ rows, h rows, consts (biases, W_out, m) ----
#pragma unroll
    for (int i = 0; i < 24; i++) {
        int idx = tid + i * 256;           // 0..6143
        int row = idx / 192, co = idx - row * 192;
        const char* src = (const char*)(g_Gpre + (size_t)(s * NSEQ + n0 + row) * NPRE)
                          + co * 16;
        cp16(sb + FS_PQ + row * (PQ_PITCH * 2) + co * 16, src);
    }
#pragma unroll
    for (int i = 0; i < 8; i++) {
        int idx = tid + i * 256;           // 0..2047
        int row = idx >> 6, co = idx & 63;
        const char* src = (const char*)(g_h + (size_t)(n0 + row) * DD) + co * 16;
        cp16(sb + FS_H + row * (H_PITCH * 4) + co * 16, src);
    }
#pragma unroll
    for (int i = 0; i < 2; i++) {
        int idx = tid + i * 256;
        if (idx < 456) {
            const char* src;
            if (idx < 192)      src = (const char*)b_ih + idx * 16;
            else if (idx < 384) src = (const char*)b_hh + (idx - 192) * 16;
            else if (idx < 448) src = (const char*)W_out + (idx - 384) * 16;
            else                src = (const char*)(g_m + n0) + (idx - 448) * 16;
            cp16(sb + FS_CON + idx * 16, src);
        }
    }
    cp_commit();

    float acc[3][8][4];
#pragma unroll
    for (int g = 0; g < 3; g++)
#pragma unroll
        for (int ni = 0; ni < 8; ni++)
#pragma unroll
            for (int q = 0; q < 4; q++) acc[g][ni][q] = 0.0f;

    const int arow  = wm * 16 + (lane & 15);
    const int acolb = (lane >> 4) * 16;
    const int brow  = wn * 64 + ((lane >> 4) << 3) + (lane & 7);
    const int bcolb = ((lane >> 3) & 1) * 16;

    // ---- GEMM loop: 12 B chunks [nt(3)][kc(4)], double-buffered ----
#pragma unroll 1
    for (int j = 0; j < 12; j++) {
        if (j < 11) {
            uint32_t dst = sb + FS_B + ((j + 1) & 1) * BBYT;
            const char* src = (const char*)g_Bh + (size_t)(j + 1) * BBYT;
#pragma unroll
            for (int i = 0; i < 8; i++) {
                int o = (tid + i * 256) * 16;
                cp16(dst + o, src + o);
            }
            cp_commit();
            cp_wait_d(j == 0 ? 2 : 1);
        } else {
            cp_wait<0>();
        }
        __syncthreads();

        const int nt = j >> 2, kc = j & 3;
        const uint32_t abase = sb + FS_A + kc * 4096;
        const uint32_t bbase = sb + FS_B + (j & 1) * BBYT;
#pragma unroll
        for (int kk = 0; kk < 4; kk++) {
            uint32_t Af[4];
            ldm4(abase + swz(arow * 128 + kk * 32 + acolb), Af);
            uint32_t Bf[4][4];
#pragma unroll
            for (int jj = 0; jj < 4; jj++)
                ldm4(bbase + swz((brow + jj * 16) * 128 + kk * 32 + bcolb), Bf[jj]);
#pragma unroll
            for (int jj = 0; jj < 4; jj++) {
                mma_fp16(acc[nt][2 * jj],     Af, Bf[jj]);
                mma_fp16(acc[nt][2 * jj + 1], Af, Bf[jj] + 2);
            }
        }
        __syncthreads();
    }

    // ---- elem phase: all inputs in smem, Gh in registers ----
    const float* CON = (const float*)(smem + FS_CON);
    float* Sy = (float*)(smem + FS_Y);
    const int r1 = wm * 16 + (lane >> 2);
    const int r2 = r1 + 8;
    const float m1 = CON[1792 + r1];   // m at CON + 7168B = float idx 1792
    const float m2 = CON[1792 + r2];
    const __half* PQ1 = (const __half*)(smem + FS_PQ) + r1 * PQ_PITCH;
    const __half* PQ2 = (const __half*)(smem + FS_PQ) + r2 * PQ_PITCH;
    float* H1 = (float*)(smem + FS_H) + r1 * H_PITCH;
    float* H2 = (float*)(smem + FS_H) + r2 * H_PITCH;
    float yp1 = 0.0f, yp2 = 0.0f;

#pragma unroll
    for (int ni = 0; ni < 8; ni++) {
        const int d = wn * 64 + ni * 8 + 2 * (lane & 3);
        float2 bir = *(const float2*)(CON + d);
        float2 biz = *(const float2*)(CON + 256 + d);
        float2 bin = *(const float2*)(CON + 512 + d);
        float2 bhr = *(const float2*)(CON + 768 + d);
        float2 bhz = *(const float2*)(CON + 1024 + d);
        float2 bhn = *(const float2*)(CON + 1280 + d);
        float2 wo  = *(const float2*)(CON + 1536 + d);
#pragma unroll
        for (int rr = 0; rr < 2; rr++) {
            const __half* PQ = rr ? PQ2 : PQ1;
            float* H = rr ? H2 : H1;
            const float mm = rr ? m2 : m1;
            const float ghr0 = acc[0][ni][rr * 2],     ghr1 = acc[0][ni][rr * 2 + 1];
            const float ghz0 = acc[1][ni][rr * 2],     ghz1 = acc[1][ni][rr * 2 + 1];
            const float ghn0 = acc[2][ni][rr * 2],     ghn1 = acc[2][ni][rr * 2 + 1];
            float2 Pr = __half22float2(*(const __half2*)(PQ + d));
            float2 Pz = __half22float2(*(const __half2*)(PQ + 256 + d));
            float2 Pn = __half22float2(*(const __half2*)(PQ + 512 + d));
            float2 Qr = __half22float2(*(const __half2*)(PQ + 768 + d));
            float2 Qz = __half22float2(*(const __half2*)(PQ + 1024 + d));
            float2 Qn = __half22float2(*(const __half2*)(PQ + 1280 + d));
            float r0 = sigmoidf_(Pr.x + mm * Qr.x + bir.x + ghr0 + bhr.x);
            float r1v = sigmoidf_(Pr.y + mm * Qr.y + bir.y + ghr1 + bhr.y);
            float z0 = sigmoidf_(Pz.x + mm * Qz.x + biz.x + ghz0 + bhz.x);
            float z1 = sigmoidf_(Pz.y + mm * Qz.y + biz.y + ghz1 + bhz.y);
            float nv0 = tanhf(Pn.x + mm * Qn.x + bin.x + r0 * (ghn0 + bhn.x));
            float nv1 = tanhf(Pn.y + mm * Qn.y + bin.y + r1v * (ghn1 + bhn.y));
            float h0 = H[d], h1 = H[d + 1];
            float hv0 = fmaf(z0, h0 - nv0, nv0);
            float hv1 = fmaf(z1, h1 - nv1, nv1);
            H[d] = hv0; H[d + 1] = hv1;
            const int row = rr ? r2 : r1;
            *(__half2*)(smem + FS_A + (d >> 6) * 4096 + swz(row * 128 + (d & 63) * 2)) =
                __floats2half2_rn(hv0, hv1);
            if (rr) yp2 = fmaf(hv0, wo.x, fmaf(hv1, wo.y, yp2));
            else    yp1 = fmaf(hv0, wo.x, fmaf(hv1, wo.y, yp1));
        }
    }
    // reduce y across the 4 lanes of each quad, then across wn via smem
    yp1 += __shfl_xor_sync(0xffffffffu, yp1, 1);
    yp1 += __shfl_xor_sync(0xffffffffu, yp1, 2);
    yp2 += __shfl_xor_sync(0xffffffffu, yp2, 1);
    yp2 += __shfl_xor_sync(0xffffffffu, yp2, 2);
    if ((lane & 3) == 0) {
        Sy[r1 * 4 + wn] = yp1;
        Sy[r2 * 4 + wn] = yp2;
    }
    __syncthreads();

    if (tid < 32) {
        float y = Sy[tid * 4] + Sy[tid * 4 + 1] + Sy[tid * 4 + 2] + Sy[tid * 4 + 3]
                  + __ldg(b_out);
        out[(n0 + tid) * SLATE_ + s] = y;
        g_m[n0 + tid] = sigmoidf_(y);
    }

    // ---- write back state: h (fp32) and next-step A (fp16, swizzled) ----
#pragma unroll
    for (int i = 0; i < 8; i++) {
        int idx = tid + i * 256;
        int row = idx >> 6, co = idx & 63;
        *(float4*)((char*)g_h + (size_t)(n0 + row) * 1024 + co * 16) =
            *(const float4*)(smem + FS_H + row * (H_PITCH * 4) + co * 16);
    }
#pragma unroll
    for (int i = 0; i < 4; i++) {
        int idx = tid + i * 256;
        int kc = idx >> 8, inner = idx & 255;
        char* dst = (char*)g_Ah + ((size_t)(n0 >> 7) * 4 + kc) * ABYT
                    + (size_t)(n0 & 127) * 128 + inner * 16;
        *(float4*)dst = *(const float4*)(smem + FS_A + idx * 16);
    }
}

extern "C" void kernel_launch(void* const* d_in, const int* in_sizes, int n_in,
                              void* d_out, int out_size) {
    const int*   item_idxs  = (const int*)d_in[0];
    const int*   user_idxs  = (const int*)d_in[1];
    /* d_in[2] = responses (unused) */
    const float* item_table = (const float*)d_in[3];
    const float* user_table = (const float*)d_in[4];
    const float* W_ih       = (const float*)d_in[5];
    const float* W_hh       = (const float*)d_in[6];
    const float* b_ih       = (const float*)d_in[7];
    const float* b_hh       = (const float*)d_in[8];
    const float* W_out      = (const float*)d_in[9];
    const float* b_out      = (const float*)d_in[10];
    float* out = (float*)d_out;

    cudaFuncSetAttribute(gemm_pre_kernel,
                         cudaFuncAttributeMaxDynamicSharedMemorySize, PRE_SMEM);
    cudaFuncSetAttribute(fused_step_kernel,
                         cudaFuncAttributeMaxDynamicSharedMemorySize, FS_TOT);

    wsplit_pre_kernel<<<NPRE * 256 / 256, 256>>>(W_ih);
    wsplit_h_kernel<<<NH * 256 / 256, 256>>>(W_hh);
    prep_e_kernel<<<MROWS_PRE / 8, 256>>>(item_idxs, item_table);
    prep_h_kernel<<<NSEQ / 8, 256>>>(user_idxs, user_table);

    gemm_pre_kernel<<<PRE_NT * PRE_CTAS_PER_NT, 256, PRE_SMEM>>>();

    for (int s = 0; s < SLATE_; s++) {
        fused_step_kernel<<<NSEQ / 32, 256, FS_TOT>>>(b_ih, b_hh, W_out, b_out, out, s);
    }
}